// round 14
// baseline (speedup 1.0000x reference)
#include <cuda_runtime.h>
#include <cuda_bf16.h>
#include <cstdint>

// Correlation (FlowNet) via per-(b,h) Gram GEMMs on mma.sync (HMMA bf16).
//   out[b, dy*81+dx, h, w] = (1/sqrt(128)) * sum_c x1[b,c,h,w]*x2pad[b,c,h+dy,w+dx]
// D[w][w2] = sum_c x1[.,h,w]*x2[.,h2,w2]  (M=96, N=96, K=128, split-bf16 x3)
// out[dy][dx][w] = D[w][w+dx-40], h2 = h+dy-40.
//
// R9: 512 threads = 12 GEMM warps (3x4 grid, 32x24 tiles, 3 warps/SMSP) +
// 4 epilogue warps; double-buffered sD; named-barrier semaphores.

#define MD 40
#define KD 81
#define C  128
#define H  64
#define W  96

#define IMG_HALF  24576                 // 96 rows * 256 B (bf16 [w][c], swizzled)
#define IMG_BYTES 49152                 // hi image + lo image

__device__ __align__(1024) unsigned char gA[(size_t)2 * H * IMG_BYTES];
__device__ __align__(1024) unsigned char gB[(size_t)2 * H * IMG_BYTES];

__device__ __forceinline__ uint32_t smem_u32(const void* p) {
    uint32_t a;
    asm("{ .reg .u64 t; cvta.to.shared.u64 t, %1; cvt.u32.u64 %0, t; }" : "=r"(a) : "l"(p));
    return a;
}
__device__ __forceinline__ uint32_t swz(int row, int kbyte) {
    uint32_t off = row * 256 + kbyte;
    return off ^ ((row & 7) << 4);
}

#define CP16(sdst, gsrc) \
    asm volatile("cp.async.cg.shared.global [%0], [%1], 16;" \
        :: "r"(sdst), "l"(gsrc) : "memory")
#define CP_COMMIT() asm volatile("cp.async.commit_group;" ::: "memory")

#define BAR_SYNC(id, cnt)   asm volatile("bar.sync %0, %1;"   :: "r"(id), "r"(cnt) : "memory")
#define BAR_ARRIVE(id, cnt) asm volatile("bar.arrive %0, %1;" :: "r"(id), "r"(cnt) : "memory")

#define LDMX4(r0,r1,r2,r3,a) \
    asm volatile("ldmatrix.sync.aligned.m8n8.x4.shared.b16 {%0,%1,%2,%3}, [%4];" \
        : "=r"(r0),"=r"(r1),"=r"(r2),"=r"(r3) : "r"(a))
#define LDMX2(r0,r1,a) \
    asm volatile("ldmatrix.sync.aligned.m8n8.x2.shared.b16 {%0,%1}, [%2];" \
        : "=r"(r0),"=r"(r1) : "r"(a))
#define MMA(d,a,b) \
    asm volatile("mma.sync.aligned.m16n8k16.row.col.f32.bf16.bf16.f32 " \
        "{%0,%1,%2,%3}, {%4,%5,%6,%7}, {%8,%9}, {%0,%1,%2,%3};" \
        : "+f"((d)[0]),"+f"((d)[1]),"+f"((d)[2]),"+f"((d)[3]) \
        : "r"((a)[0]),"r"((a)[1]),"r"((a)[2]),"r"((a)[3]), "r"((b)[0]),"r"((b)[1]))

// ---------------- kernel 1: build swizzled bf16 hi/lo images ----------------
#define STG_STRIDE 129
#define PREP_SMEM (96 * STG_STRIDE * 4 + IMG_BYTES)   // 98688

__global__ __launch_bounds__(256, 1)
void prep_kernel(const float* __restrict__ x1, const float* __restrict__ x2)
{
    extern __shared__ float ps[];
    uint32_t* img = (uint32_t*)((unsigned char*)ps + 96 * STG_STRIDE * 4);

    const int h = blockIdx.x, b = blockIdx.y, tid = threadIdx.x;

    for (int t = 0; t < 2; t++) {
        const float* src = (t ? x2 : x1);
        for (int i = tid; i < C * (W / 4); i += 256) {
            const int c = i / 24, q = i % 24;
            const float4 v = *(const float4*)(src + (((size_t)b * C + c) * H + h) * W + q * 4);
            ps[(q * 4 + 0) * STG_STRIDE + c] = v.x;
            ps[(q * 4 + 1) * STG_STRIDE + c] = v.y;
            ps[(q * 4 + 2) * STG_STRIDE + c] = v.z;
            ps[(q * 4 + 3) * STG_STRIDE + c] = v.w;
        }
        __syncthreads();
        for (int i = tid; i < W * (C / 2); i += 256) {
            const int w = i >> 6, c2 = i & 63;
            const float f0 = ps[w * STG_STRIDE + 2 * c2];
            const float f1 = ps[w * STG_STRIDE + 2 * c2 + 1];
            const __nv_bfloat16 h0 = __float2bfloat16(f0);
            const __nv_bfloat16 h1 = __float2bfloat16(f1);
            const __nv_bfloat16 l0 = __float2bfloat16(f0 - __bfloat162float(h0));
            const __nv_bfloat16 l1 = __float2bfloat16(f1 - __bfloat162float(h1));
            const uint32_t hw = ((uint32_t)__bfloat16_as_ushort(h1) << 16) | __bfloat16_as_ushort(h0);
            const uint32_t lw = ((uint32_t)__bfloat16_as_ushort(l1) << 16) | __bfloat16_as_ushort(l0);
            const uint32_t sw = swz(w, c2 * 4);
            img[sw >> 2]              = hw;
            img[(IMG_HALF + sw) >> 2] = lw;
        }
        __syncthreads();
        {
            unsigned char* gdst = (t ? gB : gA) + ((size_t)b * H + h) * IMG_BYTES;
            uint4* d4 = (uint4*)gdst;
            const uint4* s4 = (const uint4*)img;
            for (int i = tid; i < IMG_BYTES / 16; i += 256) d4[i] = s4[i];
        }
        __syncthreads();
    }
}

// ---------------- kernel 2: warp-specialized HMMA GEMM + epilogue ----------------
#define SB_OFF   IMG_BYTES
#define SD_OFF   (3 * IMG_BYTES)                 // 147456
#define DSTRIDE  104
#define SD_BYTES (96 * DSTRIDE * 4)              // 39936
#define MAIN_SMEM (SD_OFF + 2 * SD_BYTES)        // 227328
#define NT_MAIN  512
#define NPROD    384                             // 12 GEMM warps

__global__ __launch_bounds__(NT_MAIN, 1)
void corr_main(float* __restrict__ out)
{
    extern __shared__ unsigned char smem[];
    const uint32_t sb = smem_u32(smem);

    const int tid = threadIdx.x, wid = tid >> 5, lane = tid & 31;
    const int h = blockIdx.x, b = blockIdx.y;

    const int lo = (h - MD < 0) ? 0 : h - MD;
    const int hi = (h + MD > H - 1) ? H - 1 : h + MD;
    const int nv = hi - lo + 1;
    const float SCALE = 0.08838834764831843f;   // 1/sqrt(128)

    if (wid < 12) {
        // =================== producers: copies + GEMM + stage ===================
        {
            const unsigned char* ga = gA + ((size_t)b * H + h) * IMG_BYTES;
            for (int t = tid; t < IMG_BYTES / 16; t += NPROD)
                CP16(sb + t * 16, (uint64_t)__cvta_generic_to_global(ga + t * 16));
            const unsigned char* gb0 = gB + ((size_t)b * H + lo) * IMG_BYTES;
            for (int t = tid; t < IMG_BYTES / 16; t += NPROD)
                CP16(sb + SB_OFF + t * 16, (uint64_t)__cvta_generic_to_global(gb0 + t * 16));
            CP_COMMIT();
            if (nv > 1) {
                const unsigned char* gb1 = gB + ((size_t)b * H + lo + 1) * IMG_BYTES;
                for (int t = tid; t < IMG_BYTES / 16; t += NPROD)
                    CP16(sb + SB_OFF + IMG_BYTES + t * 16, (uint64_t)__cvta_generic_to_global(gb1 + t * 16));
                CP_COMMIT();
            }
        }

        // 3(M) x 4(N) warp grid, 32x24 tiles
        const int mbase = (wid >> 2) * 32;      // 0,32,64
        const int nbase = (wid & 3) * 24;       // 0,24,48,72

        const int ja = lane >> 3;
        const int ra = (lane & 7) + ((ja & 1) << 3);
        const int ka = (ja >> 1) << 4;
        const int rb = lane & 7;
        const int kb = ((lane >> 3) & 1) << 4;
        const int tq = lane >> 2, tr = (lane & 3) * 2;

        for (int i = 0; i < nv; i++) {
            const int s = i & 1;
            const uint32_t sB = sb + SB_OFF + s * IMG_BYTES;
            float* sDp = (float*)(smem + SD_OFF + s * SD_BYTES);

            if (i + 1 < nv) asm volatile("cp.async.wait_group 1;" ::: "memory");
            else            asm volatile("cp.async.wait_group 0;" ::: "memory");
            BAR_SYNC(1, NPROD);                 // B(i) visible to all producers

            // ---- GEMM: 2(M) x 3(N) frags, 3-term split-bf16, frag double-buffer ----
            float acc[2][3][4];
#pragma unroll
            for (int m = 0; m < 2; m++)
#pragma unroll
                for (int n = 0; n < 3; n++)
#pragma unroll
                    for (int j = 0; j < 4; j++) acc[m][n][j] = 0.f;

            uint32_t ah[2][2][4], al[2][2][4], bh[2][3][2], bl[2][3][2];
#pragma unroll
            for (int m = 0; m < 2; m++) {
                const uint32_t ad = sb + swz(mbase + m * 16 + ra, ka);
                LDMX4(ah[0][m][0], ah[0][m][1], ah[0][m][2], ah[0][m][3], ad);
                LDMX4(al[0][m][0], al[0][m][1], al[0][m][2], al[0][m][3], ad + IMG_HALF);
            }
#pragma unroll
            for (int n = 0; n < 3; n++) {
                const uint32_t bd = sB + swz(nbase + n * 8 + rb, kb);
                LDMX2(bh[0][n][0], bh[0][n][1], bd);
                LDMX2(bl[0][n][0], bl[0][n][1], bd + IMG_HALF);
            }

#pragma unroll
            for (int kc = 0; kc < 8; kc++) {
                const int cur = kc & 1, nxt = cur ^ 1;
                if (kc < 7) {
                    const int kn = (kc + 1) * 32;
#pragma unroll
                    for (int m = 0; m < 2; m++) {
                        const uint32_t ad = sb + swz(mbase + m * 16 + ra, kn + ka);
                        LDMX4(ah[nxt][m][0], ah[nxt][m][1], ah[nxt][m][2], ah[nxt][m][3], ad);
                        LDMX4(al[nxt][m][0], al[nxt][m][1], al[nxt][m][2], al[nxt][m][3], ad + IMG_HALF);
                    }
#pragma unroll
                    for (int n = 0; n < 3; n++) {
                        const uint32_t bd = sB + swz(nbase + n * 8 + rb, kn + kb);
                        LDMX2(bh[nxt][n][0], bh[nxt][n][1], bd);
                        LDMX2(bl[nxt][n][0], bl[nxt][n][1], bd + IMG_HALF);
                    }
                }
#pragma unroll
                for (int m = 0; m < 2; m++)
#pragma unroll
                    for (int n = 0; n < 3; n++) {
                        MMA(acc[m][n], ah[cur][m], bh[cur][n]);
                        MMA(acc[m][n], ah[cur][m], bl[cur][n]);
                        MMA(acc[m][n], al[cur][m], bh[cur][n]);
                    }
            }

            // ---- stage D (scaled) into sD[s] once it is free ----
            if (i >= 2) BAR_SYNC(4 + s, NT_MAIN);   // consumer freed this buffer
#pragma unroll
            for (int m = 0; m < 2; m++) {
                const int r = mbase + m * 16 + tq;
#pragma unroll
                for (int n = 0; n < 3; n++) {
                    const int c = nbase + n * 8 + tr;
                    *(float2*)(sDp + r * DSTRIDE + c) =
                        make_float2(acc[m][n][0] * SCALE, acc[m][n][1] * SCALE);
                    *(float2*)(sDp + (r + 8) * DSTRIDE + c) =
                        make_float2(acc[m][n][2] * SCALE, acc[m][n][3] * SCALE);
                }
            }
            BAR_ARRIVE(2 + s, NT_MAIN);             // signal full

            BAR_SYNC(1, NPROD);                     // all producers done with sB[s]
            if (i + 2 < nv) {
                const unsigned char* gbn = gB + ((size_t)b * H + lo + i + 2) * IMG_BYTES;
                for (int t = tid; t < IMG_BYTES / 16; t += NPROD)
                    CP16(sB + t * 16, (uint64_t)__cvta_generic_to_global(gbn + t * 16));
                CP_COMMIT();
            }
        }
    } else {
        // =================== consumers: zero slabs + epilogue ===================
        const int etid = tid - NPROD;               // 0..127
        const int ewid = wid - 12;                  // 0..3
        {
            const float4 z = make_float4(0.f, 0.f, 0.f, 0.f);
            for (int dy = 0; dy < KD; dy++) {
                const int h2 = h + dy - MD;
                if (h2 >= 0 && h2 < H) continue;
                const size_t base = (((size_t)b * (KD * KD) + (size_t)dy * KD) * H + h) * W;
                for (int i = etid; i < KD * (W / 4); i += 128) {
                    const int dx = i / (W / 4), q = i % (W / 4);
                    *(float4*)(out + base + (size_t)dx * (H * W) + q * 4) = z;
                }
            }
        }

        for (int i = 0; i < nv; i++) {
            const int p = i & 1;
            const float* sDp = (const float*)(smem + SD_OFF + p * SD_BYTES);
            BAR_SYNC(2 + p, NT_MAIN);               // wait full

            const int dy = (lo + i) - h + MD;
            const size_t obase = (((size_t)b * (KD * KD) + (size_t)dy * KD) * H + h) * W;
            for (int dx = ewid; dx < KD; dx += 4) {
                const int d0 = dx - MD;
#pragma unroll
                for (int wc = 0; wc < 3; wc++) {
                    const int w = wc * 32 + lane, w2 = w + d0;
                    const float v = (w2 >= 0 && w2 < W) ? sDp[w * DSTRIDE + w2] : 0.f;
                    out[obase + (size_t)dx * (H * W) + w] = v;
                }
            }
            BAR_ARRIVE(4 + p, NT_MAIN);             // signal empty
        }
    }
}

// ---------------- launch ----------------
extern "C" void kernel_launch(void* const* d_in, const int* in_sizes, int n_in,
                              void* d_out, int out_size)
{
    const float* x1 = (const float*)d_in[0];
    const float* x2 = (const float*)d_in[1];
    float* out = (float*)d_out;

    cudaFuncSetAttribute(prep_kernel, cudaFuncAttributeMaxDynamicSharedMemorySize, PREP_SMEM);
    cudaFuncSetAttribute(corr_main,   cudaFuncAttributeMaxDynamicSharedMemorySize, MAIN_SMEM);

    dim3 grid(H, 2);
    prep_kernel<<<grid, 256, PREP_SMEM>>>(x1, x2);
    corr_main<<<grid, NT_MAIN, MAIN_SMEM>>>(out);
}

// round 15
// speedup vs baseline: 1.2419x; 1.2419x over previous
#include <cuda_runtime.h>
#include <cuda_fp16.h>
#include <cstdint>

// Correlation (FlowNet) via per-(b,h) Gram GEMMs on mma.sync (HMMA fp16).
//   out[b, dy*81+dx, h, w] = (1/sqrt(128)) * sum_c x1[b,c,h,w]*x2pad[b,c,h+dy,w+dx]
// D[w][w2] = sum_c x1[.,h,w]*x2[.,h2,w2]  (M=96, N=96, K=128)
// fp16 2-term: D = A_hi*B_hi + A_hi*B_lo = A_hi*x2 ; error = (x1-A_hi)·x2 ~ 2.8e-4.
//
// R10: 512 threads = 12 GEMM warps (3x4 grid, 32x24 tiles) + 4 epilogue warps;
// A image fp16-hi only (24KB), B image fp16 hi+lo (48KB); double-buffered sD.

#define MD 40
#define KD 81
#define C  128
#define H  64
#define W  96

#define IMG_HALF  24576                 // 96 rows * 256 B (fp16 [w][c], swizzled)
#define A_BYTES   24576                 // hi only
#define B_BYTES   49152                 // hi + lo

__device__ __align__(1024) unsigned char gA[(size_t)2 * H * A_BYTES];
__device__ __align__(1024) unsigned char gB[(size_t)2 * H * B_BYTES];

__device__ __forceinline__ uint32_t smem_u32(const void* p) {
    uint32_t a;
    asm("{ .reg .u64 t; cvta.to.shared.u64 t, %1; cvt.u32.u64 %0, t; }" : "=r"(a) : "l"(p));
    return a;
}
__device__ __forceinline__ uint32_t swz(int row, int kbyte) {
    uint32_t off = row * 256 + kbyte;
    return off ^ ((row & 7) << 4);
}

#define CP16(sdst, gsrc) \
    asm volatile("cp.async.cg.shared.global [%0], [%1], 16;" \
        :: "r"(sdst), "l"(gsrc) : "memory")
#define CP_COMMIT() asm volatile("cp.async.commit_group;" ::: "memory")

#define BAR_SYNC(id, cnt)   asm volatile("bar.sync %0, %1;"   :: "r"(id), "r"(cnt) : "memory")
#define BAR_ARRIVE(id, cnt) asm volatile("bar.arrive %0, %1;" :: "r"(id), "r"(cnt) : "memory")

#define LDMX4(r0,r1,r2,r3,a) \
    asm volatile("ldmatrix.sync.aligned.m8n8.x4.shared.b16 {%0,%1,%2,%3}, [%4];" \
        : "=r"(r0),"=r"(r1),"=r"(r2),"=r"(r3) : "r"(a))
#define LDMX2(r0,r1,a) \
    asm volatile("ldmatrix.sync.aligned.m8n8.x2.shared.b16 {%0,%1}, [%2];" \
        : "=r"(r0),"=r"(r1) : "r"(a))
#define MMA(d,a,b) \
    asm volatile("mma.sync.aligned.m16n8k16.row.col.f32.f16.f16.f32 " \
        "{%0,%1,%2,%3}, {%4,%5,%6,%7}, {%8,%9}, {%0,%1,%2,%3};" \
        : "+f"((d)[0]),"+f"((d)[1]),"+f"((d)[2]),"+f"((d)[3]) \
        : "r"((a)[0]),"r"((a)[1]),"r"((a)[2]),"r"((a)[3]), "r"((b)[0]),"r"((b)[1]))

// ---------------- kernel 1: build swizzled fp16 images ----------------
#define STG_STRIDE 129
#define PREP_SMEM (96 * STG_STRIDE * 4 + B_BYTES)   // 49536 + 49152 = 98688

__global__ __launch_bounds__(256, 1)
void prep_kernel(const float* __restrict__ x1, const float* __restrict__ x2)
{
    extern __shared__ float ps[];
    uint32_t* img = (uint32_t*)((unsigned char*)ps + 96 * STG_STRIDE * 4);

    const int h = blockIdx.x, b = blockIdx.y, tid = threadIdx.x;

    for (int t = 0; t < 2; t++) {
        const float* src = (t ? x2 : x1);
        for (int i = tid; i < C * (W / 4); i += 256) {
            const int c = i / 24, q = i % 24;
            const float4 v = *(const float4*)(src + (((size_t)b * C + c) * H + h) * W + q * 4);
            ps[(q * 4 + 0) * STG_STRIDE + c] = v.x;
            ps[(q * 4 + 1) * STG_STRIDE + c] = v.y;
            ps[(q * 4 + 2) * STG_STRIDE + c] = v.z;
            ps[(q * 4 + 3) * STG_STRIDE + c] = v.w;
        }
        __syncthreads();
        for (int i = tid; i < W * (C / 2); i += 256) {
            const int w = i >> 6, c2 = i & 63;
            const float f0 = ps[w * STG_STRIDE + 2 * c2];
            const float f1 = ps[w * STG_STRIDE + 2 * c2 + 1];
            const __half h0 = __float2half_rn(f0);
            const __half h1 = __float2half_rn(f1);
            const uint32_t hw = ((uint32_t)__half_as_ushort(h1) << 16) | __half_as_ushort(h0);
            const uint32_t sw = swz(w, c2 * 4);
            img[sw >> 2] = hw;
            if (t) {    // B image also needs the lo residual
                const __half l0 = __float2half_rn(f0 - __half2float(h0));
                const __half l1 = __float2half_rn(f1 - __half2float(h1));
                const uint32_t lw = ((uint32_t)__half_as_ushort(l1) << 16) | __half_as_ushort(l0);
                img[(IMG_HALF + sw) >> 2] = lw;
            }
        }
        __syncthreads();
        {
            const int nbytes = t ? B_BYTES : A_BYTES;
            unsigned char* gdst = t ? (gB + ((size_t)b * H + h) * B_BYTES)
                                    : (gA + ((size_t)b * H + h) * A_BYTES);
            uint4* d4 = (uint4*)gdst;
            const uint4* s4 = (const uint4*)img;
            for (int i = tid; i < nbytes / 16; i += 256) d4[i] = s4[i];
        }
        __syncthreads();
    }
}

// ---------------- kernel 2: warp-specialized HMMA GEMM + epilogue ----------------
#define SB_OFF   A_BYTES                          // 24576
#define SD_OFF   (A_BYTES + 2 * B_BYTES)          // 122880
#define DSTRIDE  104
#define SD_BYTES (96 * DSTRIDE * 4)               // 39936
#define MAIN_SMEM (SD_OFF + 2 * SD_BYTES)         // 202752
#define NT_MAIN  512
#define NPROD    384                              // 12 GEMM warps

__global__ __launch_bounds__(NT_MAIN, 1)
void corr_main(float* __restrict__ out)
{
    extern __shared__ unsigned char smem[];
    const uint32_t sb = smem_u32(smem);

    const int tid = threadIdx.x, wid = tid >> 5, lane = tid & 31;
    const int h = blockIdx.x, b = blockIdx.y;

    const int lo = (h - MD < 0) ? 0 : h - MD;
    const int hi = (h + MD > H - 1) ? H - 1 : h + MD;
    const int nv = hi - lo + 1;
    const float SCALE = 0.08838834764831843f;   // 1/sqrt(128)

    if (wid < 12) {
        // =================== producers: copies + GEMM + stage ===================
        {
            const unsigned char* ga = gA + ((size_t)b * H + h) * A_BYTES;
            for (int t = tid; t < A_BYTES / 16; t += NPROD)
                CP16(sb + t * 16, (uint64_t)__cvta_generic_to_global(ga + t * 16));
            const unsigned char* gb0 = gB + ((size_t)b * H + lo) * B_BYTES;
            for (int t = tid; t < B_BYTES / 16; t += NPROD)
                CP16(sb + SB_OFF + t * 16, (uint64_t)__cvta_generic_to_global(gb0 + t * 16));
            CP_COMMIT();
            if (nv > 1) {
                const unsigned char* gb1 = gB + ((size_t)b * H + lo + 1) * B_BYTES;
                for (int t = tid; t < B_BYTES / 16; t += NPROD)
                    CP16(sb + SB_OFF + B_BYTES + t * 16, (uint64_t)__cvta_generic_to_global(gb1 + t * 16));
                CP_COMMIT();
            }
        }

        // 3(M) x 4(N) warp grid, 32x24 tiles
        const int mbase = (wid >> 2) * 32;      // 0,32,64
        const int nbase = (wid & 3) * 24;       // 0,24,48,72

        const int ja = lane >> 3;
        const int ra = (lane & 7) + ((ja & 1) << 3);
        const int ka = (ja >> 1) << 4;
        const int rb = lane & 7;
        const int kb = ((lane >> 3) & 1) << 4;
        const int tq = lane >> 2, tr = (lane & 3) * 2;

        for (int i = 0; i < nv; i++) {
            const int s = i & 1;
            const uint32_t sB = sb + SB_OFF + s * B_BYTES;
            float* sDp = (float*)(smem + SD_OFF + s * SD_BYTES);

            if (i + 1 < nv) asm volatile("cp.async.wait_group 1;" ::: "memory");
            else            asm volatile("cp.async.wait_group 0;" ::: "memory");
            BAR_SYNC(1, NPROD);                 // B(i) visible to all producers

            // ---- GEMM: 2(M) x 3(N) frags, fp16 2-term, frag double-buffer ----
            float acc[2][3][4];
#pragma unroll
            for (int m = 0; m < 2; m++)
#pragma unroll
                for (int n = 0; n < 3; n++)
#pragma unroll
                    for (int j = 0; j < 4; j++) acc[m][n][j] = 0.f;

            uint32_t ah[2][2][4], bh[2][3][2], bl[2][3][2];
#pragma unroll
            for (int m = 0; m < 2; m++) {
                const uint32_t ad = sb + swz(mbase + m * 16 + ra, ka);
                LDMX4(ah[0][m][0], ah[0][m][1], ah[0][m][2], ah[0][m][3], ad);
            }
#pragma unroll
            for (int n = 0; n < 3; n++) {
                const uint32_t bd = sB + swz(nbase + n * 8 + rb, kb);
                LDMX2(bh[0][n][0], bh[0][n][1], bd);
                LDMX2(bl[0][n][0], bl[0][n][1], bd + IMG_HALF);
            }

#pragma unroll
            for (int kc = 0; kc < 8; kc++) {
                const int cur = kc & 1, nxt = cur ^ 1;
                if (kc < 7) {
                    const int kn = (kc + 1) * 32;
#pragma unroll
                    for (int m = 0; m < 2; m++) {
                        const uint32_t ad = sb + swz(mbase + m * 16 + ra, kn + ka);
                        LDMX4(ah[nxt][m][0], ah[nxt][m][1], ah[nxt][m][2], ah[nxt][m][3], ad);
                    }
#pragma unroll
                    for (int n = 0; n < 3; n++) {
                        const uint32_t bd = sB + swz(nbase + n * 8 + rb, kn + kb);
                        LDMX2(bh[nxt][n][0], bh[nxt][n][1], bd);
                        LDMX2(bl[nxt][n][0], bl[nxt][n][1], bd + IMG_HALF);
                    }
                }
#pragma unroll
                for (int m = 0; m < 2; m++)
#pragma unroll
                    for (int n = 0; n < 3; n++) {
                        MMA(acc[m][n], ah[cur][m], bh[cur][n]);
                        MMA(acc[m][n], ah[cur][m], bl[cur][n]);
                    }
            }

            // ---- stage D (scaled) into sD[s] once it is free ----
            if (i >= 2) BAR_SYNC(4 + s, NT_MAIN);   // consumer freed this buffer
#pragma unroll
            for (int m = 0; m < 2; m++) {
                const int r = mbase + m * 16 + tq;
#pragma unroll
                for (int n = 0; n < 3; n++) {
                    const int c = nbase + n * 8 + tr;
                    *(float2*)(sDp + r * DSTRIDE + c) =
                        make_float2(acc[m][n][0] * SCALE, acc[m][n][1] * SCALE);
                    *(float2*)(sDp + (r + 8) * DSTRIDE + c) =
                        make_float2(acc[m][n][2] * SCALE, acc[m][n][3] * SCALE);
                }
            }
            BAR_ARRIVE(2 + s, NT_MAIN);             // signal full

            BAR_SYNC(1, NPROD);                     // all producers done with sB[s]
            if (i + 2 < nv) {
                const unsigned char* gbn = gB + ((size_t)b * H + lo + i + 2) * B_BYTES;
                for (int t = tid; t < B_BYTES / 16; t += NPROD)
                    CP16(sB + t * 16, (uint64_t)__cvta_generic_to_global(gbn + t * 16));
                CP_COMMIT();
            }
        }
    } else {
        // =================== consumers: zero slabs + epilogue ===================
        const int etid = tid - NPROD;               // 0..127
        const int ewid = wid - 12;                  // 0..3
        {
            const float4 z = make_float4(0.f, 0.f, 0.f, 0.f);
            for (int dy = 0; dy < KD; dy++) {
                const int h2 = h + dy - MD;
                if (h2 >= 0 && h2 < H) continue;
                const size_t base = (((size_t)b * (KD * KD) + (size_t)dy * KD) * H + h) * W;
                for (int i = etid; i < KD * (W / 4); i += 128) {
                    const int dx = i / (W / 4), q = i % (W / 4);
                    *(float4*)(out + base + (size_t)dx * (H * W) + q * 4) = z;
                }
            }
        }

        for (int i = 0; i < nv; i++) {
            const int p = i & 1;
            const float* sDp = (const float*)(smem + SD_OFF + p * SD_BYTES);
            BAR_SYNC(2 + p, NT_MAIN);               // wait full

            const int dy = (lo + i) - h + MD;
            const size_t obase = (((size_t)b * (KD * KD) + (size_t)dy * KD) * H + h) * W;
            for (int dx = ewid; dx < KD; dx += 4) {
                const int d0 = dx - MD;
#pragma unroll
                for (int wc = 0; wc < 3; wc++) {
                    const int w = wc * 32 + lane, w2 = w + d0;
                    const float v = (w2 >= 0 && w2 < W) ? sDp[w * DSTRIDE + w2] : 0.f;
                    out[obase + (size_t)dx * (H * W) + w] = v;
                }
            }
            BAR_ARRIVE(4 + p, NT_MAIN);             // signal empty
        }
    }
}

// ---------------- launch ----------------
extern "C" void kernel_launch(void* const* d_in, const int* in_sizes, int n_in,
                              void* d_out, int out_size)
{
    const float* x1 = (const float*)d_in[0];
    const float* x2 = (const float*)d_in[1];
    float* out = (float*)d_out;

    cudaFuncSetAttribute(prep_kernel, cudaFuncAttributeMaxDynamicSharedMemorySize, PREP_SMEM);
    cudaFuncSetAttribute(corr_main,   cudaFuncAttributeMaxDynamicSharedMemorySize, MAIN_SMEM);

    dim3 grid(H, 2);
    prep_kernel<<<grid, 256, PREP_SMEM>>>(x1, x2);
    corr_main<<<grid, NT_MAIN, MAIN_SMEM>>>(out);
}

// round 16
// speedup vs baseline: 1.3447x; 1.0828x over previous
#include <cuda_runtime.h>
#include <cuda_fp16.h>
#include <cstdint>

// Correlation (FlowNet) via per-(b,h) Gram GEMMs on mma.sync (HMMA fp16).
//   out[b, dy*81+dx, h, w] = (1/sqrt(128)) * sum_c x1[b,c,h,w]*x2pad[b,c,h+dy,w+dx]
// D[w][w2] = sum_c x1[.,h,w]*(s*x2)[.,h2,w2]  (M=96, N=96, K=128), s=1/sqrt(128)
// fp16 2-term: A_hi*(B_hi+B_lo) = A_hi*(s*x2); error = (x1-A_hi)·s·x2 ~ 2e-4.
//
// R11: A fragments hoisted to registers (loop-invariant, 64 regs), scale baked
// into B image; 512 threads = 12 GEMM warps (3x4, 32x24) + 4 epilogue warps.

#define MD 40
#define KD 81
#define C  128
#define H  64
#define W  96

#define IMG_HALF  24576                 // 96 rows * 256 B (fp16 [w][c], swizzled)
#define A_BYTES   24576                 // hi only
#define B_BYTES   49152                 // hi + lo

__device__ __align__(1024) unsigned char gA[(size_t)2 * H * A_BYTES];
__device__ __align__(1024) unsigned char gB[(size_t)2 * H * B_BYTES];

__device__ __forceinline__ uint32_t smem_u32(const void* p) {
    uint32_t a;
    asm("{ .reg .u64 t; cvta.to.shared.u64 t, %1; cvt.u32.u64 %0, t; }" : "=r"(a) : "l"(p));
    return a;
}
__device__ __forceinline__ uint32_t swz(int row, int kbyte) {
    uint32_t off = row * 256 + kbyte;
    return off ^ ((row & 7) << 4);
}

#define CP16(sdst, gsrc) \
    asm volatile("cp.async.cg.shared.global [%0], [%1], 16;" \
        :: "r"(sdst), "l"(gsrc) : "memory")
#define CP_COMMIT() asm volatile("cp.async.commit_group;" ::: "memory")

#define BAR_SYNC(id, cnt)   asm volatile("bar.sync %0, %1;"   :: "r"(id), "r"(cnt) : "memory")
#define BAR_ARRIVE(id, cnt) asm volatile("bar.arrive %0, %1;" :: "r"(id), "r"(cnt) : "memory")

#define LDMX4(r0,r1,r2,r3,a) \
    asm volatile("ldmatrix.sync.aligned.m8n8.x4.shared.b16 {%0,%1,%2,%3}, [%4];" \
        : "=r"(r0),"=r"(r1),"=r"(r2),"=r"(r3) : "r"(a))
#define LDMX2(r0,r1,a) \
    asm volatile("ldmatrix.sync.aligned.m8n8.x2.shared.b16 {%0,%1}, [%2];" \
        : "=r"(r0),"=r"(r1) : "r"(a))
#define MMA(d,a,b) \
    asm volatile("mma.sync.aligned.m16n8k16.row.col.f32.f16.f16.f32 " \
        "{%0,%1,%2,%3}, {%4,%5,%6,%7}, {%8,%9}, {%0,%1,%2,%3};" \
        : "+f"((d)[0]),"+f"((d)[1]),"+f"((d)[2]),"+f"((d)[3]) \
        : "r"((a)[0]),"r"((a)[1]),"r"((a)[2]),"r"((a)[3]), "r"((b)[0]),"r"((b)[1]))

// ---------------- kernel 1: build swizzled fp16 images ----------------
#define STG_STRIDE 129
#define PREP_SMEM (96 * STG_STRIDE * 4 + B_BYTES)   // 98688

__global__ __launch_bounds__(256, 1)
void prep_kernel(const float* __restrict__ x1, const float* __restrict__ x2)
{
    extern __shared__ float ps[];
    uint32_t* img = (uint32_t*)((unsigned char*)ps + 96 * STG_STRIDE * 4);

    const int h = blockIdx.x, b = blockIdx.y, tid = threadIdx.x;
    const float SCALE = 0.08838834764831843f;   // 1/sqrt(128), folded into B

    for (int t = 0; t < 2; t++) {
        const float* src = (t ? x2 : x1);
        for (int i = tid; i < C * (W / 4); i += 256) {
            const int c = i / 24, q = i % 24;
            const float4 v = *(const float4*)(src + (((size_t)b * C + c) * H + h) * W + q * 4);
            ps[(q * 4 + 0) * STG_STRIDE + c] = v.x;
            ps[(q * 4 + 1) * STG_STRIDE + c] = v.y;
            ps[(q * 4 + 2) * STG_STRIDE + c] = v.z;
            ps[(q * 4 + 3) * STG_STRIDE + c] = v.w;
        }
        __syncthreads();
        for (int i = tid; i < W * (C / 2); i += 256) {
            const int w = i >> 6, c2 = i & 63;
            float f0 = ps[w * STG_STRIDE + 2 * c2];
            float f1 = ps[w * STG_STRIDE + 2 * c2 + 1];
            if (t) { f0 *= SCALE; f1 *= SCALE; }
            const __half h0 = __float2half_rn(f0);
            const __half h1 = __float2half_rn(f1);
            const uint32_t hw = ((uint32_t)__half_as_ushort(h1) << 16) | __half_as_ushort(h0);
            const uint32_t sw = swz(w, c2 * 4);
            img[sw >> 2] = hw;
            if (t) {    // B image also carries the lo residual
                const __half l0 = __float2half_rn(f0 - __half2float(h0));
                const __half l1 = __float2half_rn(f1 - __half2float(h1));
                const uint32_t lw = ((uint32_t)__half_as_ushort(l1) << 16) | __half_as_ushort(l0);
                img[(IMG_HALF + sw) >> 2] = lw;
            }
        }
        __syncthreads();
        {
            const int nbytes = t ? B_BYTES : A_BYTES;
            unsigned char* gdst = t ? (gB + ((size_t)b * H + h) * B_BYTES)
                                    : (gA + ((size_t)b * H + h) * A_BYTES);
            uint4* d4 = (uint4*)gdst;
            const uint4* s4 = (const uint4*)img;
            for (int i = tid; i < nbytes / 16; i += 256) d4[i] = s4[i];
        }
        __syncthreads();
    }
}

// ---------------- kernel 2: warp-specialized HMMA GEMM + epilogue ----------------
#define SB_OFF   A_BYTES                          // 24576
#define SD_OFF   (A_BYTES + 2 * B_BYTES)          // 122880
#define DSTRIDE  104
#define SD_BYTES (96 * DSTRIDE * 4)               // 39936
#define MAIN_SMEM (SD_OFF + 2 * SD_BYTES)         // 202752
#define NT_MAIN  512
#define NPROD    384                              // 12 GEMM warps

__global__ __launch_bounds__(NT_MAIN, 1)
void corr_main(float* __restrict__ out)
{
    extern __shared__ unsigned char smem[];
    const uint32_t sb = smem_u32(smem);

    const int tid = threadIdx.x, wid = tid >> 5, lane = tid & 31;
    const int h = blockIdx.x, b = blockIdx.y;

    const int lo = (h - MD < 0) ? 0 : h - MD;
    const int hi = (h + MD > H - 1) ? H - 1 : h + MD;
    const int nv = hi - lo + 1;                   // always >= 41

    if (wid < 12) {
        // =================== producers: copies + GEMM + stage ===================
        {
            const unsigned char* ga = gA + ((size_t)b * H + h) * A_BYTES;
            for (int t = tid; t < A_BYTES / 16; t += NPROD)
                CP16(sb + t * 16, (uint64_t)__cvta_generic_to_global(ga + t * 16));
            const unsigned char* gb0 = gB + ((size_t)b * H + lo) * B_BYTES;
            for (int t = tid; t < B_BYTES / 16; t += NPROD)
                CP16(sb + SB_OFF + t * 16, (uint64_t)__cvta_generic_to_global(gb0 + t * 16));
            CP_COMMIT();
            {
                const unsigned char* gb1 = gB + ((size_t)b * H + lo + 1) * B_BYTES;
                for (int t = tid; t < B_BYTES / 16; t += NPROD)
                    CP16(sb + SB_OFF + B_BYTES + t * 16, (uint64_t)__cvta_generic_to_global(gb1 + t * 16));
                CP_COMMIT();
            }
        }

        // 3(M) x 4(N) warp grid, 32x24 tiles
        const int mbase = (wid >> 2) * 32;      // 0,32,64
        const int nbase = (wid & 3) * 24;       // 0,24,48,72

        const int ja = lane >> 3;
        const int ra = (lane & 7) + ((ja & 1) << 3);
        const int ka = (ja >> 1) << 4;
        const int rb = lane & 7;
        const int kb = ((lane >> 3) & 1) << 4;
        const int tq = lane >> 2, tr = (lane & 3) * 2;

        // ---- A image ready (group 0 done); preload ALL A fragments ----
        asm volatile("cp.async.wait_group 1;" ::: "memory");
        BAR_SYNC(1, NPROD);

        uint32_t ah[8][2][4];                    // loop-invariant across h2
#pragma unroll
        for (int kc = 0; kc < 8; kc++)
#pragma unroll
            for (int m = 0; m < 2; m++) {
                const uint32_t ad = sb + swz(mbase + m * 16 + ra, kc * 32 + ka);
                LDMX4(ah[kc][m][0], ah[kc][m][1], ah[kc][m][2], ah[kc][m][3], ad);
            }

        for (int i = 0; i < nv; i++) {
            const int s = i & 1;
            const uint32_t sB = sb + SB_OFF + s * B_BYTES;
            float* sDp = (float*)(smem + SD_OFF + s * SD_BYTES);

            if (i > 0) {
                if (i + 1 < nv) asm volatile("cp.async.wait_group 1;" ::: "memory");
                else            asm volatile("cp.async.wait_group 0;" ::: "memory");
                BAR_SYNC(1, NPROD);             // B(i) visible to all producers
            }

            // ---- GEMM: 2(M) x 3(N) frags, fp16 2-term, B-frag double buffer ----
            float acc[2][3][4];
#pragma unroll
            for (int m = 0; m < 2; m++)
#pragma unroll
                for (int n = 0; n < 3; n++)
#pragma unroll
                    for (int j = 0; j < 4; j++) acc[m][n][j] = 0.f;

            uint32_t bh[2][3][2], bl[2][3][2];
#pragma unroll
            for (int n = 0; n < 3; n++) {
                const uint32_t bd = sB + swz(nbase + n * 8 + rb, kb);
                LDMX2(bh[0][n][0], bh[0][n][1], bd);
                LDMX2(bl[0][n][0], bl[0][n][1], bd + IMG_HALF);
            }

#pragma unroll
            for (int kc = 0; kc < 8; kc++) {
                const int cur = kc & 1, nxt = cur ^ 1;
                if (kc < 7) {
                    const int kn = (kc + 1) * 32;
#pragma unroll
                    for (int n = 0; n < 3; n++) {
                        const uint32_t bd = sB + swz(nbase + n * 8 + rb, kn + kb);
                        LDMX2(bh[nxt][n][0], bh[nxt][n][1], bd);
                        LDMX2(bl[nxt][n][0], bl[nxt][n][1], bd + IMG_HALF);
                    }
                }
#pragma unroll
                for (int m = 0; m < 2; m++)
#pragma unroll
                    for (int n = 0; n < 3; n++) {
                        MMA(acc[m][n], ah[kc][m], bh[cur][n]);
                        MMA(acc[m][n], ah[kc][m], bl[cur][n]);
                    }
            }

            // ---- stage D into sD[s] once it is free (scale pre-baked in B) ----
            if (i >= 2) BAR_SYNC(4 + s, NT_MAIN);   // consumer freed this buffer
#pragma unroll
            for (int m = 0; m < 2; m++) {
                const int r = mbase + m * 16 + tq;
#pragma unroll
                for (int n = 0; n < 3; n++) {
                    const int c = nbase + n * 8 + tr;
                    *(float2*)(sDp + r * DSTRIDE + c) =
                        make_float2(acc[m][n][0], acc[m][n][1]);
                    *(float2*)(sDp + (r + 8) * DSTRIDE + c) =
                        make_float2(acc[m][n][2], acc[m][n][3]);
                }
            }
            BAR_ARRIVE(2 + s, NT_MAIN);             // signal full

            BAR_SYNC(1, NPROD);                     // all producers done with sB[s]
            if (i + 2 < nv) {
                const unsigned char* gbn = gB + ((size_t)b * H + lo + i + 2) * B_BYTES;
                for (int t = tid; t < B_BYTES / 16; t += NPROD)
                    CP16(sB + t * 16, (uint64_t)__cvta_generic_to_global(gbn + t * 16));
                CP_COMMIT();
            }
        }
    } else {
        // =================== consumers: zero slabs + epilogue ===================
        const int etid = tid - NPROD;               // 0..127
        const int ewid = wid - 12;                  // 0..3
        {
            const float4 z = make_float4(0.f, 0.f, 0.f, 0.f);
            for (int dy = 0; dy < KD; dy++) {
                const int h2 = h + dy - MD;
                if (h2 >= 0 && h2 < H) continue;
                const size_t base = (((size_t)b * (KD * KD) + (size_t)dy * KD) * H + h) * W;
                for (int i = etid; i < KD * (W / 4); i += 128) {
                    const int dx = i / (W / 4), q = i % (W / 4);
                    *(float4*)(out + base + (size_t)dx * (H * W) + q * 4) = z;
                }
            }
        }

        for (int i = 0; i < nv; i++) {
            const int p = i & 1;
            const float* sDp = (const float*)(smem + SD_OFF + p * SD_BYTES);
            BAR_SYNC(2 + p, NT_MAIN);               // wait full

            const int dy = (lo + i) - h + MD;
            const size_t obase = (((size_t)b * (KD * KD) + (size_t)dy * KD) * H + h) * W;
            for (int dx = ewid; dx < KD; dx += 4) {
                const int d0 = dx - MD;
#pragma unroll
                for (int wc = 0; wc < 3; wc++) {
                    const int w = wc * 32 + lane, w2 = w + d0;
                    const float v = (w2 >= 0 && w2 < W) ? sDp[w * DSTRIDE + w2] : 0.f;
                    out[obase + (size_t)dx * (H * W) + w] = v;
                }
            }
            BAR_ARRIVE(4 + p, NT_MAIN);             // signal empty
        }
    }
}

// ---------------- launch ----------------
extern "C" void kernel_launch(void* const* d_in, const int* in_sizes, int n_in,
                              void* d_out, int out_size)
{
    const float* x1 = (const float*)d_in[0];
    const float* x2 = (const float*)d_in[1];
    float* out = (float*)d_out;

    cudaFuncSetAttribute(prep_kernel, cudaFuncAttributeMaxDynamicSharedMemorySize, PREP_SMEM);
    cudaFuncSetAttribute(corr_main,   cudaFuncAttributeMaxDynamicSharedMemorySize, MAIN_SMEM);

    dim3 grid(H, 2);
    prep_kernel<<<grid, 256, PREP_SMEM>>>(x1, x2);
    corr_main<<<grid, NT_MAIN, MAIN_SMEM>>>(out);
}

// round 17
// speedup vs baseline: 1.7976x; 1.3368x over previous
#include <cuda_runtime.h>
#include <cuda_fp16.h>
#include <cstdint>

// Correlation (FlowNet) via per-(b,h) Gram GEMMs on mma.sync (HMMA fp16).
//   out[b, dy*81+dx, h, w] = (1/sqrt(128)) * sum_c x1[b,c,h,w]*x2pad[b,c,h+dy,w+dx]
// D[w][w2] = sum_c x1[.,h,w]*(s*x2)[.,h2,w2]  (M=96, N=96, K=128), s=1/sqrt(128)
// R12: 1-term fp16 (A_hi * B_hi). error ~ l_A·B + A·l_B ~ 2.9e-4 << 1e-3.
// 512 threads = 12 GEMM warps (3x4, 32x24, A frags hoisted) + 4 epilogue warps.

#define MD 40
#define KD 81
#define C  128
#define H  64
#define W  96

#define IMG_BYTES 24576                 // 96 rows * 256 B (fp16 [w][c], swizzled)

__device__ __align__(1024) unsigned char gA[(size_t)2 * H * IMG_BYTES];
__device__ __align__(1024) unsigned char gB[(size_t)2 * H * IMG_BYTES];

__device__ __forceinline__ uint32_t smem_u32(const void* p) {
    uint32_t a;
    asm("{ .reg .u64 t; cvta.to.shared.u64 t, %1; cvt.u32.u64 %0, t; }" : "=r"(a) : "l"(p));
    return a;
}
__device__ __forceinline__ uint32_t swz(int row, int kbyte) {
    uint32_t off = row * 256 + kbyte;
    return off ^ ((row & 7) << 4);
}

#define CP16(sdst, gsrc) \
    asm volatile("cp.async.cg.shared.global [%0], [%1], 16;" \
        :: "r"(sdst), "l"(gsrc) : "memory")
#define CP_COMMIT() asm volatile("cp.async.commit_group;" ::: "memory")

#define BAR_SYNC(id, cnt)   asm volatile("bar.sync %0, %1;"   :: "r"(id), "r"(cnt) : "memory")
#define BAR_ARRIVE(id, cnt) asm volatile("bar.arrive %0, %1;" :: "r"(id), "r"(cnt) : "memory")

#define LDMX4(r0,r1,r2,r3,a) \
    asm volatile("ldmatrix.sync.aligned.m8n8.x4.shared.b16 {%0,%1,%2,%3}, [%4];" \
        : "=r"(r0),"=r"(r1),"=r"(r2),"=r"(r3) : "r"(a))
#define LDMX2(r0,r1,a) \
    asm volatile("ldmatrix.sync.aligned.m8n8.x2.shared.b16 {%0,%1}, [%2];" \
        : "=r"(r0),"=r"(r1) : "r"(a))
#define MMA(d,a,b) \
    asm volatile("mma.sync.aligned.m16n8k16.row.col.f32.f16.f16.f32 " \
        "{%0,%1,%2,%3}, {%4,%5,%6,%7}, {%8,%9}, {%0,%1,%2,%3};" \
        : "+f"((d)[0]),"+f"((d)[1]),"+f"((d)[2]),"+f"((d)[3]) \
        : "r"((a)[0]),"r"((a)[1]),"r"((a)[2]),"r"((a)[3]), "r"((b)[0]),"r"((b)[1]))

// ---------------- kernel 1: build swizzled fp16 images (hi only) ----------------
#define STG_STRIDE 129
#define PREP_SMEM (96 * STG_STRIDE * 4 + IMG_BYTES)   // 74112

__global__ __launch_bounds__(256, 1)
void prep_kernel(const float* __restrict__ x1, const float* __restrict__ x2)
{
    extern __shared__ float ps[];
    uint32_t* img = (uint32_t*)((unsigned char*)ps + 96 * STG_STRIDE * 4);

    const int h = blockIdx.x, b = blockIdx.y, tid = threadIdx.x;
    const float SCALE = 0.08838834764831843f;   // 1/sqrt(128), folded into B

    for (int t = 0; t < 2; t++) {
        const float* src = (t ? x2 : x1);
        for (int i = tid; i < C * (W / 4); i += 256) {
            const int c = i / 24, q = i % 24;
            const float4 v = *(const float4*)(src + (((size_t)b * C + c) * H + h) * W + q * 4);
            ps[(q * 4 + 0) * STG_STRIDE + c] = v.x;
            ps[(q * 4 + 1) * STG_STRIDE + c] = v.y;
            ps[(q * 4 + 2) * STG_STRIDE + c] = v.z;
            ps[(q * 4 + 3) * STG_STRIDE + c] = v.w;
        }
        __syncthreads();
        for (int i = tid; i < W * (C / 2); i += 256) {
            const int w = i >> 6, c2 = i & 63;
            float f0 = ps[w * STG_STRIDE + 2 * c2];
            float f1 = ps[w * STG_STRIDE + 2 * c2 + 1];
            if (t) { f0 *= SCALE; f1 *= SCALE; }
            const __half h0 = __float2half_rn(f0);
            const __half h1 = __float2half_rn(f1);
            const uint32_t hw = ((uint32_t)__half_as_ushort(h1) << 16) | __half_as_ushort(h0);
            img[swz(w, c2 * 4) >> 2] = hw;
        }
        __syncthreads();
        {
            unsigned char* gdst = (t ? gB : gA) + ((size_t)b * H + h) * IMG_BYTES;
            uint4* d4 = (uint4*)gdst;
            const uint4* s4 = (const uint4*)img;
            for (int i = tid; i < IMG_BYTES / 16; i += 256) d4[i] = s4[i];
        }
        __syncthreads();
    }
}

// ---------------- kernel 2: warp-specialized HMMA GEMM + epilogue ----------------
#define SB_OFF   IMG_BYTES                        // 24576
#define SD_OFF   (3 * IMG_BYTES)                  // 73728
#define DSTRIDE  104
#define SD_BYTES (96 * DSTRIDE * 4)               // 39936
#define MAIN_SMEM (SD_OFF + 2 * SD_BYTES)         // 153600
#define NT_MAIN  512
#define NPROD    384                              // 12 GEMM warps

__global__ __launch_bounds__(NT_MAIN, 1)
void corr_main(float* __restrict__ out)
{
    extern __shared__ unsigned char smem[];
    const uint32_t sb = smem_u32(smem);

    const int tid = threadIdx.x, wid = tid >> 5, lane = tid & 31;
    const int h = blockIdx.x, b = blockIdx.y;

    const int lo = (h - MD < 0) ? 0 : h - MD;
    const int hi = (h + MD > H - 1) ? H - 1 : h + MD;
    const int nv = hi - lo + 1;                   // 41..64

    if (wid < 12) {
        // =================== producers: copies + GEMM + stage ===================
        {
            const unsigned char* ga = gA + ((size_t)b * H + h) * IMG_BYTES;
            for (int t = tid; t < IMG_BYTES / 16; t += NPROD)
                CP16(sb + t * 16, (uint64_t)__cvta_generic_to_global(ga + t * 16));
            const unsigned char* gb0 = gB + ((size_t)b * H + lo) * IMG_BYTES;
            for (int t = tid; t < IMG_BYTES / 16; t += NPROD)
                CP16(sb + SB_OFF + t * 16, (uint64_t)__cvta_generic_to_global(gb0 + t * 16));
            CP_COMMIT();
            {
                const unsigned char* gb1 = gB + ((size_t)b * H + lo + 1) * IMG_BYTES;
                for (int t = tid; t < IMG_BYTES / 16; t += NPROD)
                    CP16(sb + SB_OFF + IMG_BYTES + t * 16, (uint64_t)__cvta_generic_to_global(gb1 + t * 16));
                CP_COMMIT();
            }
        }

        // 3(M) x 4(N) warp grid, 32x24 tiles
        const int mbase = (wid >> 2) * 32;      // 0,32,64
        const int nbase = (wid & 3) * 24;       // 0,24,48,72

        const int ja = lane >> 3;
        const int ra = (lane & 7) + ((ja & 1) << 3);
        const int ka = (ja >> 1) << 4;
        const int rb = lane & 7;
        const int kb = ((lane >> 3) & 1) << 4;
        const int tq = lane >> 2, tr = (lane & 3) * 2;

        // ---- A image ready (group 0 done); preload ALL A fragments ----
        asm volatile("cp.async.wait_group 1;" ::: "memory");
        BAR_SYNC(1, NPROD);

        uint32_t ah[8][2][4];                    // loop-invariant across h2
#pragma unroll
        for (int kc = 0; kc < 8; kc++)
#pragma unroll
            for (int m = 0; m < 2; m++) {
                const uint32_t ad = sb + swz(mbase + m * 16 + ra, kc * 32 + ka);
                LDMX4(ah[kc][m][0], ah[kc][m][1], ah[kc][m][2], ah[kc][m][3], ad);
            }

        for (int i = 0; i < nv; i++) {
            const int s = i & 1;
            const uint32_t sB = sb + SB_OFF + s * IMG_BYTES;
            float* sDp = (float*)(smem + SD_OFF + s * SD_BYTES);

            if (i > 0) {
                if (i + 1 < nv) asm volatile("cp.async.wait_group 1;" ::: "memory");
                else            asm volatile("cp.async.wait_group 0;" ::: "memory");
                BAR_SYNC(1, NPROD);             // B(i) visible to all producers
            }

            // ---- GEMM: 2(M) x 3(N) frags, 1-term fp16, B-frag double buffer ----
            float acc[2][3][4];
#pragma unroll
            for (int m = 0; m < 2; m++)
#pragma unroll
                for (int n = 0; n < 3; n++)
#pragma unroll
                    for (int j = 0; j < 4; j++) acc[m][n][j] = 0.f;

            uint32_t bh[2][3][2];
#pragma unroll
            for (int n = 0; n < 3; n++) {
                const uint32_t bd = sB + swz(nbase + n * 8 + rb, kb);
                LDMX2(bh[0][n][0], bh[0][n][1], bd);
            }

#pragma unroll
            for (int kc = 0; kc < 8; kc++) {
                const int cur = kc & 1, nxt = cur ^ 1;
                if (kc < 7) {
                    const int kn = (kc + 1) * 32;
#pragma unroll
                    for (int n = 0; n < 3; n++) {
                        const uint32_t bd = sB + swz(nbase + n * 8 + rb, kn + kb);
                        LDMX2(bh[nxt][n][0], bh[nxt][n][1], bd);
                    }
                }
#pragma unroll
                for (int m = 0; m < 2; m++)
#pragma unroll
                    for (int n = 0; n < 3; n++)
                        MMA(acc[m][n], ah[kc][m], bh[cur][n]);
            }

            // ---- stage D into sD[s] once it is free (scale pre-baked in B) ----
            if (i >= 2) BAR_SYNC(4 + s, NT_MAIN);   // consumer freed this buffer
#pragma unroll
            for (int m = 0; m < 2; m++) {
                const int r = mbase + m * 16 + tq;
#pragma unroll
                for (int n = 0; n < 3; n++) {
                    const int c = nbase + n * 8 + tr;
                    *(float2*)(sDp + r * DSTRIDE + c) =
                        make_float2(acc[m][n][0], acc[m][n][1]);
                    *(float2*)(sDp + (r + 8) * DSTRIDE + c) =
                        make_float2(acc[m][n][2], acc[m][n][3]);
                }
            }
            BAR_ARRIVE(2 + s, NT_MAIN);             // signal full

            BAR_SYNC(1, NPROD);                     // all producers done with sB[s]
            if (i + 2 < nv) {
                const unsigned char* gbn = gB + ((size_t)b * H + lo + i + 2) * IMG_BYTES;
                for (int t = tid; t < IMG_BYTES / 16; t += NPROD)
                    CP16(sB + t * 16, (uint64_t)__cvta_generic_to_global(gbn + t * 16));
                CP_COMMIT();
            }
        }
    } else {
        // =================== consumers: zero slabs + epilogue ===================
        const int etid = tid - NPROD;               // 0..127
        const int ewid = wid - 12;                  // 0..3
        {
            const float4 z = make_float4(0.f, 0.f, 0.f, 0.f);
            for (int dy = 0; dy < KD; dy++) {
                const int h2 = h + dy - MD;
                if (h2 >= 0 && h2 < H) continue;
                const size_t base = (((size_t)b * (KD * KD) + (size_t)dy * KD) * H + h) * W;
                for (int i = etid; i < KD * (W / 4); i += 128) {
                    const int dx = i / (W / 4), q = i % (W / 4);
                    *(float4*)(out + base + (size_t)dx * (H * W) + q * 4) = z;
                }
            }
        }

        for (int i = 0; i < nv; i++) {
            const int p = i & 1;
            const float* sDp = (const float*)(smem + SD_OFF + p * SD_BYTES);
            BAR_SYNC(2 + p, NT_MAIN);               // wait full

            const int dy = (lo + i) - h + MD;
            const size_t obase = (((size_t)b * (KD * KD) + (size_t)dy * KD) * H + h) * W;
            for (int dx = ewid; dx < KD; dx += 4) {
                const int d0 = dx - MD;
#pragma unroll
                for (int wc = 0; wc < 3; wc++) {
                    const int w = wc * 32 + lane, w2 = w + d0;
                    const float v = (w2 >= 0 && w2 < W) ? sDp[w * DSTRIDE + w2] : 0.f;
                    out[obase + (size_t)dx * (H * W) + w] = v;
                }
            }
            BAR_ARRIVE(4 + p, NT_MAIN);             // signal empty
        }
    }
}

// ---------------- launch ----------------
extern "C" void kernel_launch(void* const* d_in, const int* in_sizes, int n_in,
                              void* d_out, int out_size)
{
    const float* x1 = (const float*)d_in[0];
    const float* x2 = (const float*)d_in[1];
    float* out = (float*)d_out;

    cudaFuncSetAttribute(prep_kernel, cudaFuncAttributeMaxDynamicSharedMemorySize, PREP_SMEM);
    cudaFuncSetAttribute(corr_main,   cudaFuncAttributeMaxDynamicSharedMemorySize, MAIN_SMEM);

    dim3 grid(H, 2);
    prep_kernel<<<grid, 256, PREP_SMEM>>>(x1, x2);
    corr_main<<<grid, NT_MAIN, MAIN_SMEM>>>(out);
}